// round 1
// baseline (speedup 1.0000x reference)
#include <cuda_runtime.h>
#include <mma.h>

using namespace nvcuda;

#define B_SZ   512
#define N_TOK  196
#define HEADS  8
#define DH     64
#define QSCALE 0.125f

// ---------------- scratch (no allocs allowed) ----------------
__device__ float g_qkv[(size_t)B_SZ * N_TOK * 1536];  // 616 MB
__device__ float g_att[(size_t)B_SZ * N_TOK * 512];   // 205 MB

// ---------------- generic tf32 GEMM + bias: C[M,N] = A[M,K] @ W[K,N] + bias ----------------
#define GBM 128
#define GBN 64
#define GBK 32
#define A_STR 40   // 32 + 8 pad, rows stay 16B aligned
#define B_STR 72   // 64 + 8 pad
#define C_STR 68   // 64 + 4 pad (272B rows, 16B aligned)

__global__ void __launch_bounds__(256) gemm_bias_kernel(
    const float* __restrict__ A, const float* __restrict__ W,
    const float* __restrict__ bias, float* __restrict__ C,
    int M, int Nn, int K)
{
    extern __shared__ float sm[];
    float* As = sm;                      // 128*40 = 5120
    float* Bs = sm + GBM * A_STR;        // 32*72  = 2304
    float* Cs = sm;                      // reuse: 128*68 = 8704

    const int tid  = threadIdx.x;
    const int warp = tid >> 5;
    const int wm   = warp >> 1;          // 0..3
    const int wn   = warp & 1;           // 0..1
    const size_t m0 = (size_t)blockIdx.x * GBM;
    const int    n0 = blockIdx.y * GBN;

    wmma::fragment<wmma::accumulator, 16, 16, 8, float> acc[2][2];
#pragma unroll
    for (int i = 0; i < 2; i++)
#pragma unroll
        for (int j = 0; j < 2; j++) wmma::fill_fragment(acc[i][j], 0.f);

    const int ar = tid >> 3, ac = (tid & 7) * 4;    // A tile loader
    const int br = tid >> 4, bc = (tid & 15) * 4;   // B tile loader

    for (int k0 = 0; k0 < K; k0 += GBK) {
#pragma unroll
        for (int rr = 0; rr < 4; rr++) {
            float4 v = *(const float4*)&A[(m0 + ar + rr * 32) * K + k0 + ac];
            *(float4*)&As[(ar + rr * 32) * A_STR + ac] = v;
        }
#pragma unroll
        for (int rr = 0; rr < 2; rr++) {
            float4 v = *(const float4*)&W[(size_t)(k0 + br + rr * 16) * Nn + n0 + bc];
            *(float4*)&Bs[(br + rr * 16) * B_STR + bc] = v;
        }
        __syncthreads();

#pragma unroll
        for (int kk = 0; kk < GBK; kk += 8) {
            wmma::fragment<wmma::matrix_a, 16, 16, 8, wmma::precision::tf32, wmma::row_major> af[2];
            wmma::fragment<wmma::matrix_b, 16, 16, 8, wmma::precision::tf32, wmma::row_major> bf[2];
#pragma unroll
            for (int i = 0; i < 2; i++) {
                wmma::load_matrix_sync(af[i], &As[(wm * 32 + i * 16) * A_STR + kk], A_STR);
#pragma unroll
                for (int t = 0; t < af[i].num_elements; t++)
                    af[i].x[t] = wmma::__float_to_tf32(af[i].x[t]);
            }
#pragma unroll
            for (int j = 0; j < 2; j++) {
                wmma::load_matrix_sync(bf[j], &Bs[kk * B_STR + wn * 32 + j * 16], B_STR);
#pragma unroll
                for (int t = 0; t < bf[j].num_elements; t++)
                    bf[j].x[t] = wmma::__float_to_tf32(bf[j].x[t]);
            }
#pragma unroll
            for (int i = 0; i < 2; i++)
#pragma unroll
                for (int j = 0; j < 2; j++)
                    wmma::mma_sync(acc[i][j], af[i], bf[j], acc[i][j]);
        }
        __syncthreads();
    }

#pragma unroll
    for (int i = 0; i < 2; i++)
#pragma unroll
        for (int j = 0; j < 2; j++)
            wmma::store_matrix_sync(&Cs[(wm * 32 + i * 16) * C_STR + wn * 32 + j * 16],
                                    acc[i][j], C_STR, wmma::mem_row_major);
    __syncthreads();

    const int cr = tid >> 4, cc = (tid & 15) * 4;
#pragma unroll
    for (int rr = 0; rr < 8; rr++) {
        int r = cr + rr * 16;
        float4 v  = *(float4*)&Cs[r * C_STR + cc];
        float4 bv = *(const float4*)&bias[n0 + cc];
        v.x += bv.x; v.y += bv.y; v.z += bv.z; v.w += bv.w;
        *(float4*)&C[(m0 + r) * Nn + n0 + cc] = v;
    }
}

// ---------------- fused window attention: one CTA per (b, h) ----------------
#define KV_STR 68
#define SB_STR 216

__global__ void __launch_bounds__(256) attn_kernel(
    const float* __restrict__ qkv, const float* __restrict__ bias_table,
    float* __restrict__ att)
{
    extern __shared__ float sm[];
    float* Ks    = sm;                        // 208 * 68
    float* Vs    = Ks + 208 * KV_STR;         // 208 * 68
    float* Qb    = Vs + 208 * KV_STR;         // 16 * 68
    float* Sb    = Qb + 16 * KV_STR;          // 16 * 216
    float* Ob    = Sb + 16 * SB_STR;          // 16 * 68
    float* biasS = Ob + 16 * KV_STR;          // 729 (+pad)

    const int tid  = threadIdx.x;
    const int lane = tid & 31;
    const int warp = tid >> 5;
    const int b = blockIdx.x >> 3;
    const int h = blockIdx.x & 7;

    const float* base = qkv + (size_t)b * N_TOK * 1536 + h * DH;

    // ---- load K, V into smem (padded rows zeroed) ----
    for (int idx = tid; idx < N_TOK * 16; idx += 256) {
        int r = idx >> 4, c = (idx & 15) << 2;
        const float* rp = base + (size_t)r * 1536;
        float4 kv = *(const float4*)(rp + 512 + c);
        float4 vv = *(const float4*)(rp + 1024 + c);
        *(float4*)&Ks[r * KV_STR + c] = kv;
        *(float4*)&Vs[r * KV_STR + c] = vv;
    }
    for (int idx = tid; idx < 12 * 64; idx += 256) {
        int r = 196 + (idx >> 6), c = idx & 63;
        Ks[r * KV_STR + c] = 0.f;
        Vs[r * KV_STR + c] = 0.f;
    }
    for (int t = tid; t < 729; t += 256) biasS[t] = bias_table[t * HEADS + h];
    __syncthreads();

    for (int ib = 0; ib < 13; ib++) {
        // ---- load Q band (pre-scaled) ----
        {
            int r = tid >> 4, c = (tid & 15) << 2;
            int i = ib * 16 + r;
            float4 q = make_float4(0.f, 0.f, 0.f, 0.f);
            if (i < N_TOK) {
                q = *(const float4*)(base + (size_t)i * 1536 + c);
                q.x *= QSCALE; q.y *= QSCALE; q.z *= QSCALE; q.w *= QSCALE;
            }
            *(float4*)&Qb[r * KV_STR + c] = q;
        }
        __syncthreads();

        // ---- scores: S = Qb @ K^T  (tf32 wmma) ----
        for (int jt = warp; jt < 13; jt += 8) {
            wmma::fragment<wmma::accumulator, 16, 16, 8, float> acc;
            wmma::fill_fragment(acc, 0.f);
#pragma unroll
            for (int dk = 0; dk < DH; dk += 8) {
                wmma::fragment<wmma::matrix_a, 16, 16, 8, wmma::precision::tf32, wmma::row_major> af;
                wmma::fragment<wmma::matrix_b, 16, 16, 8, wmma::precision::tf32, wmma::col_major> bf;
                wmma::load_matrix_sync(af, &Qb[dk], KV_STR);
                wmma::load_matrix_sync(bf, &Ks[jt * 16 * KV_STR + dk], KV_STR);
#pragma unroll
                for (int t = 0; t < af.num_elements; t++) af.x[t] = wmma::__float_to_tf32(af.x[t]);
#pragma unroll
                for (int t = 0; t < bf.num_elements; t++) bf.x[t] = wmma::__float_to_tf32(bf.x[t]);
                wmma::mma_sync(acc, af, bf, acc);
            }
            wmma::store_matrix_sync(&Sb[jt * 16], acc, SB_STR, wmma::mem_row_major);
        }
        __syncthreads();

        // ---- softmax + relative-position bias (warp per row) ----
#pragma unroll
        for (int rr = 0; rr < 2; rr++) {
            int r = warp + rr * 8;
            int i = ib * 16 + r;
            float* srow = &Sb[r * SB_STR];
            if (i < N_TOK) {
                int iq = i / 14, ir = i - iq * 14;
                float mx = -1e30f;
                for (int j = lane; j < N_TOK; j += 32) {
                    int jq = j / 14, jr = j - jq * 14;
                    float t = srow[j] + biasS[(iq - jq + 13) * 27 + (ir - jr + 13)];
                    srow[j] = t;
                    mx = fmaxf(mx, t);
                }
#pragma unroll
                for (int o = 16; o > 0; o >>= 1) mx = fmaxf(mx, __shfl_xor_sync(0xffffffffu, mx, o));
                float sum = 0.f;
                for (int j = lane; j < N_TOK; j += 32) {
                    float p = __expf(srow[j] - mx);
                    srow[j] = p;
                    sum += p;
                }
#pragma unroll
                for (int o = 16; o > 0; o >>= 1) sum += __shfl_xor_sync(0xffffffffu, sum, o);
                float rinv = __frcp_rn(sum);
                for (int j = lane; j < N_TOK; j += 32) srow[j] *= rinv;
                if (lane < 12) srow[196 + lane] = 0.f;
            } else {
                for (int j = lane; j < 208; j += 32) srow[j] = 0.f;
            }
        }
        __syncthreads();

        // ---- O band = P @ V (tf32 wmma), warps 0..3 ----
        if (warp < 4) {
            wmma::fragment<wmma::accumulator, 16, 16, 8, float> oacc;
            wmma::fill_fragment(oacc, 0.f);
#pragma unroll
            for (int k8 = 0; k8 < 208; k8 += 8) {
                wmma::fragment<wmma::matrix_a, 16, 16, 8, wmma::precision::tf32, wmma::row_major> af;
                wmma::fragment<wmma::matrix_b, 16, 16, 8, wmma::precision::tf32, wmma::row_major> bf;
                wmma::load_matrix_sync(af, &Sb[k8], SB_STR);
                wmma::load_matrix_sync(bf, &Vs[k8 * KV_STR + warp * 16], KV_STR);
#pragma unroll
                for (int t = 0; t < af.num_elements; t++) af.x[t] = wmma::__float_to_tf32(af.x[t]);
#pragma unroll
                for (int t = 0; t < bf.num_elements; t++) bf.x[t] = wmma::__float_to_tf32(bf.x[t]);
                wmma::mma_sync(oacc, af, bf, oacc);
            }
            wmma::store_matrix_sync(&Ob[warp * 16], oacc, KV_STR, wmma::mem_row_major);
        }
        __syncthreads();

        // ---- write O band back (head-interleaved [B, N, D]) ----
        {
            int r = tid >> 4, c = (tid & 15) << 2;
            int i = ib * 16 + r;
            if (i < N_TOK) {
                float4 v = *(float4*)&Ob[r * KV_STR + c];
                *(float4*)&att[(size_t)(b * N_TOK + i) * 512 + h * DH + c] = v;
            }
        }
        __syncthreads();
    }
}

// ---------------- launcher ----------------
extern "C" void kernel_launch(void* const* d_in, const int* in_sizes, int n_in,
                              void* d_out, int out_size)
{
    const float* x          = (const float*)d_in[0];
    const float* w_qkv      = (const float*)d_in[1];
    const float* b_qkv      = (const float*)d_in[2];
    const float* w_proj     = (const float*)d_in[3];
    const float* b_proj     = (const float*)d_in[4];
    const float* bias_table = (const float*)d_in[5];
    float* out = (float*)d_out;

    float *qkv, *att;
    cudaGetSymbolAddress((void**)&qkv, g_qkv);
    cudaGetSymbolAddress((void**)&att, g_att);

    const int M = B_SZ * N_TOK;  // 100352
    const size_t GEMM_SMEM = (size_t)128 * C_STR * sizeof(float);  // 34816 B
    const size_t ATT_SMEM  = (size_t)(208 * KV_STR * 2 + 16 * KV_STR * 2 +
                                      16 * SB_STR + 736) * sizeof(float);  // ~138.6 KB

    cudaFuncSetAttribute(attn_kernel, cudaFuncAttributeMaxDynamicSharedMemorySize,
                         (int)ATT_SMEM);

    gemm_bias_kernel<<<dim3(M / GBM, 1536 / GBN), 256, GEMM_SMEM>>>(
        x, w_qkv, b_qkv, qkv, M, 1536, 512);

    attn_kernel<<<B_SZ * HEADS, 256, ATT_SMEM>>>(qkv, bias_table, att);

    gemm_bias_kernel<<<dim3(M / GBM, 512 / GBN), 256, GEMM_SMEM>>>(
        att, w_proj, b_proj, out, M, 512, 512);
}

// round 2
// speedup vs baseline: 1.3425x; 1.3425x over previous
#include <cuda_runtime.h>
#include <mma.h>

using namespace nvcuda;

#define B_SZ   512
#define N_TOK  196
#define HEADS  8
#define DH     64
#define QSCALE 0.125f

// ---------------- scratch (no allocs allowed) ----------------
__device__ float g_qkv[(size_t)B_SZ * N_TOK * 1536];  // 616 MB
__device__ float g_att[(size_t)B_SZ * N_TOK * 512];   // 205 MB

// ---------------- cp.async helpers ----------------
__device__ __forceinline__ void cp_async16(void* smem, const void* gmem) {
    unsigned s = (unsigned)__cvta_generic_to_shared(smem);
    asm volatile("cp.async.cg.shared.global [%0], [%1], 16;\n" :: "r"(s), "l"(gmem));
}
__device__ __forceinline__ void cp_commit() { asm volatile("cp.async.commit_group;\n"); }
template<int N> __device__ __forceinline__ void cp_wait() {
    asm volatile("cp.async.wait_group %0;\n" :: "n"(N));
}

// ---------------- tf32 GEMM + bias, 3-stage cp.async pipeline ----------------
// C[M,N] = A[M,K] @ W[K,N] + bias ;  tiles 128x128x16
#define BM 128
#define BN 128
#define BK 16
#define STAGES 3
#define ASTR 24          // 16 + 8 pad (96B rows)
#define BSTR 136         // 128 + 8 pad (544B rows)
#define CSTR 132         // 128 + 4 pad
#define AS_SZ (BM * ASTR)      // 3072 floats
#define BS_SZ (BK * BSTR)      // 2176 floats
#define STAGE_SZ (AS_SZ + BS_SZ)

__global__ void __launch_bounds__(256) gemm_bias_kernel(
    const float* __restrict__ A, const float* __restrict__ W,
    const float* __restrict__ bias, float* __restrict__ C,
    int M, int Nn, int K)
{
    extern __shared__ float sm[];
    const int tid  = threadIdx.x;
    const int warp = tid >> 5;
    const int wm   = warp >> 2;     // 0..1  (64 rows each)
    const int wn   = warp & 3;      // 0..3  (32 cols each)
    const size_t m0 = (size_t)blockIdx.x * BM;
    const int    n0 = blockIdx.y * BN;

    const int ar = tid >> 2,  acol = (tid & 3) * 4;     // A loader: 64 rows/pass
    const int br = tid >> 5,  bcol = (tid & 31) * 4;    // B loader: 8 rows/pass

    auto load_tile = [&](int stage, int kt) {
        float* As = sm + stage * STAGE_SZ;
        float* Bs = As + AS_SZ;
        int k0 = kt * BK;
        cp_async16(&As[ar * ASTR + acol],        &A[(m0 + ar) * K + k0 + acol]);
        cp_async16(&As[(ar + 64) * ASTR + acol], &A[(m0 + ar + 64) * K + k0 + acol]);
        cp_async16(&Bs[br * BSTR + bcol],        &W[(size_t)(k0 + br) * Nn + n0 + bcol]);
        cp_async16(&Bs[(br + 8) * BSTR + bcol],  &W[(size_t)(k0 + br + 8) * Nn + n0 + bcol]);
        cp_commit();
    };

    wmma::fragment<wmma::accumulator, 16, 16, 8, float> acc[4][2];
#pragma unroll
    for (int i = 0; i < 4; i++)
#pragma unroll
        for (int j = 0; j < 2; j++) wmma::fill_fragment(acc[i][j], 0.f);

    const int KT = K / BK;
#pragma unroll
    for (int s = 0; s < STAGES - 1; s++) load_tile(s, s);

    for (int kt = 0; kt < KT; kt++) {
        if (kt <= KT - STAGES) cp_wait<STAGES - 2>(); else cp_wait<0>();
        __syncthreads();

        float* As = sm + (kt % STAGES) * STAGE_SZ;
        float* Bs = As + AS_SZ;
#pragma unroll
        for (int kk = 0; kk < BK; kk += 8) {
            wmma::fragment<wmma::matrix_a, 16, 16, 8, wmma::precision::tf32, wmma::row_major> af[4];
            wmma::fragment<wmma::matrix_b, 16, 16, 8, wmma::precision::tf32, wmma::row_major> bf[2];
#pragma unroll
            for (int i = 0; i < 4; i++) {
                wmma::load_matrix_sync(af[i], &As[(wm * 64 + i * 16) * ASTR + kk], ASTR);
#pragma unroll
                for (int t = 0; t < af[i].num_elements; t++)
                    af[i].x[t] = wmma::__float_to_tf32(af[i].x[t]);
            }
#pragma unroll
            for (int j = 0; j < 2; j++) {
                wmma::load_matrix_sync(bf[j], &Bs[kk * BSTR + wn * 32 + j * 16], BSTR);
#pragma unroll
                for (int t = 0; t < bf[j].num_elements; t++)
                    bf[j].x[t] = wmma::__float_to_tf32(bf[j].x[t]);
            }
#pragma unroll
            for (int i = 0; i < 4; i++)
#pragma unroll
                for (int j = 0; j < 2; j++)
                    wmma::mma_sync(acc[i][j], af[i], bf[j], acc[i][j]);
        }
        __syncthreads();

        int nt = kt + STAGES - 1;
        if (nt < KT) load_tile(nt % STAGES, nt);
    }

    // epilogue through smem (reuse pipeline smem) for coalesced + bias
    float* Cs = sm;
#pragma unroll
    for (int i = 0; i < 4; i++)
#pragma unroll
        for (int j = 0; j < 2; j++)
            wmma::store_matrix_sync(&Cs[(wm * 64 + i * 16) * CSTR + wn * 32 + j * 16],
                                    acc[i][j], CSTR, wmma::mem_row_major);
    __syncthreads();

    const int cr = tid >> 5, cc = (tid & 31) * 4;
#pragma unroll
    for (int it = 0; it < 16; it++) {
        int r = cr + it * 8;
        float4 v  = *(float4*)&Cs[r * CSTR + cc];
        float4 bv = *(const float4*)&bias[n0 + cc];
        v.x += bv.x; v.y += bv.y; v.z += bv.z; v.w += bv.w;
        *(float4*)&C[(m0 + r) * Nn + n0 + cc] = v;
    }
}

// ---------------- fused window attention: one CTA per (b, h), 512 threads ----------------
#define KV_STR 68
#define SB_STR 216

__global__ void __launch_bounds__(512) attn_kernel(
    const float* __restrict__ qkv, const float* __restrict__ bias_table,
    float* __restrict__ att)
{
    extern __shared__ float sm[];
    float* Ks    = sm;                        // 208 * 68 = 14144
    float* Vs    = Ks  + 208 * KV_STR;        // 14144
    float* Qb    = Vs  + 208 * KV_STR;        // 32 * 68 = 2176
    float* Sb    = Qb  + 32 * KV_STR;         // 32 * 216 = 6912
    float* Ob0   = Sb  + 32 * SB_STR;         // 2176
    float* Ob1   = Ob0 + 32 * KV_STR;         // 2176
    float* biasS = Ob1 + 32 * KV_STR;         // 736

    const int tid  = threadIdx.x;
    const int lane = tid & 31;
    const int warp = tid >> 5;                // 0..15
    const int b = blockIdx.x >> 3;
    const int h = blockIdx.x & 7;

    const float* base = qkv + (size_t)b * N_TOK * 1536 + h * DH;

    // ---- load K, V into smem ----
    for (int idx = tid; idx < N_TOK * 16; idx += 512) {
        int r = idx >> 4, c = (idx & 15) << 2;
        const float* rp = base + (size_t)r * 1536;
        *(float4*)&Ks[r * KV_STR + c] = *(const float4*)(rp + 512 + c);
        *(float4*)&Vs[r * KV_STR + c] = *(const float4*)(rp + 1024 + c);
    }
    for (int idx = tid; idx < 12 * 16; idx += 512) {
        int r = 196 + (idx >> 4), c = (idx & 15) << 2;
        float4 z = make_float4(0.f, 0.f, 0.f, 0.f);
        *(float4*)&Ks[r * KV_STR + c] = z;
        *(float4*)&Vs[r * KV_STR + c] = z;
    }
    for (int t = tid; t < 729; t += 512) biasS[t] = bias_table[t * HEADS + h];
    __syncthreads();

    for (int ib = 0; ib < 7; ib++) {
        const int i0 = ib * 32;

        // ---- Q band (pre-scaled): 32x64 = one float4 per thread ----
        {
            int r = tid >> 4, c = (tid & 15) << 2;
            int i = i0 + r;
            float4 q = make_float4(0.f, 0.f, 0.f, 0.f);
            if (i < N_TOK) {
                q = *(const float4*)(base + (size_t)i * 1536 + c);
                q.x *= QSCALE; q.y *= QSCALE; q.z *= QSCALE; q.w *= QSCALE;
            }
            *(float4*)&Qb[r * KV_STR + c] = q;
        }
        __syncthreads();

        // ---- scores: S[32][208] = Qb @ Ks^T ; 26 tiles over 16 warps ----
        for (int t = warp; t < 26; t += 16) {
            int tm = t & 1, tj = t >> 1;
            wmma::fragment<wmma::accumulator, 16, 16, 8, float> acc;
            wmma::fill_fragment(acc, 0.f);
#pragma unroll
            for (int dk = 0; dk < DH; dk += 8) {
                wmma::fragment<wmma::matrix_a, 16, 16, 8, wmma::precision::tf32, wmma::row_major> af;
                wmma::fragment<wmma::matrix_b, 16, 16, 8, wmma::precision::tf32, wmma::col_major> bf;
                wmma::load_matrix_sync(af, &Qb[tm * 16 * KV_STR + dk], KV_STR);
                wmma::load_matrix_sync(bf, &Ks[tj * 16 * KV_STR + dk], KV_STR);
#pragma unroll
                for (int t2 = 0; t2 < af.num_elements; t2++) af.x[t2] = wmma::__float_to_tf32(af.x[t2]);
#pragma unroll
                for (int t2 = 0; t2 < bf.num_elements; t2++) bf.x[t2] = wmma::__float_to_tf32(bf.x[t2]);
                wmma::mma_sync(acc, af, bf, acc);
            }
            wmma::store_matrix_sync(&Sb[tm * 16 * SB_STR + tj * 16], acc, SB_STR, wmma::mem_row_major);
        }
        __syncthreads();

        // ---- softmax + bias: 2 rows per warp ----
#pragma unroll
        for (int rr = 0; rr < 2; rr++) {
            int r = warp + rr * 16;
            int i = i0 + r;
            float* srow = &Sb[r * SB_STR];
            if (i < N_TOK) {
                int iq = i / 14, ir = i - iq * 14;
                float mx = -1e30f;
                for (int j = lane; j < N_TOK; j += 32) {
                    int jq = j / 14, jr = j - jq * 14;
                    float t = srow[j] + biasS[(iq - jq + 13) * 27 + (ir - jr + 13)];
                    srow[j] = t;
                    mx = fmaxf(mx, t);
                }
#pragma unroll
                for (int o = 16; o > 0; o >>= 1) mx = fmaxf(mx, __shfl_xor_sync(0xffffffffu, mx, o));
                float sum = 0.f;
                for (int j = lane; j < N_TOK; j += 32) {
                    float p = __expf(srow[j] - mx);
                    srow[j] = p;
                    sum += p;
                }
#pragma unroll
                for (int o = 16; o > 0; o >>= 1) sum += __shfl_xor_sync(0xffffffffu, sum, o);
                float rinv = __frcp_rn(sum);
                for (int j = lane; j < N_TOK; j += 32) srow[j] *= rinv;
                if (lane < 12) srow[196 + lane] = 0.f;
            } else {
                for (int j = lane; j < 208; j += 32) srow[j] = 0.f;
            }
        }
        __syncthreads();

        // ---- O = P @ V, k-split over 2 halves; 8 tiles x 2 halves = 16 warps ----
        {
            int tile = warp >> 1, half = warp & 1;
            int tm = tile >> 2, tn = tile & 3;
            wmma::fragment<wmma::accumulator, 16, 16, 8, float> oacc;
            wmma::fill_fragment(oacc, 0.f);
            int kbase = half * 104;
#pragma unroll
            for (int s = 0; s < 13; s++) {
                int k8 = kbase + s * 8;
                wmma::fragment<wmma::matrix_a, 16, 16, 8, wmma::precision::tf32, wmma::row_major> af;
                wmma::fragment<wmma::matrix_b, 16, 16, 8, wmma::precision::tf32, wmma::row_major> bf;
                wmma::load_matrix_sync(af, &Sb[tm * 16 * SB_STR + k8], SB_STR);
                wmma::load_matrix_sync(bf, &Vs[k8 * KV_STR + tn * 16], KV_STR);
#pragma unroll
                for (int t2 = 0; t2 < af.num_elements; t2++) af.x[t2] = wmma::__float_to_tf32(af.x[t2]);
#pragma unroll
                for (int t2 = 0; t2 < bf.num_elements; t2++) bf.x[t2] = wmma::__float_to_tf32(bf.x[t2]);
                wmma::mma_sync(oacc, af, bf, oacc);
            }
            float* Ob = half ? Ob1 : Ob0;
            wmma::store_matrix_sync(&Ob[tm * 16 * KV_STR + tn * 16], oacc, KV_STR, wmma::mem_row_major);
        }
        __syncthreads();

        // ---- writeback: merge halves, head-interleaved [B, N, D] ----
        {
            int r = tid >> 4, c = (tid & 15) << 2;
            int i = i0 + r;
            if (i < N_TOK) {
                float4 a = *(float4*)&Ob0[r * KV_STR + c];
                float4 b2 = *(float4*)&Ob1[r * KV_STR + c];
                a.x += b2.x; a.y += b2.y; a.z += b2.z; a.w += b2.w;
                *(float4*)&att[(size_t)(b * N_TOK + i) * 512 + h * DH + c] = a;
            }
        }
        __syncthreads();
    }
}

// ---------------- launcher ----------------
extern "C" void kernel_launch(void* const* d_in, const int* in_sizes, int n_in,
                              void* d_out, int out_size)
{
    const float* x          = (const float*)d_in[0];
    const float* w_qkv      = (const float*)d_in[1];
    const float* b_qkv      = (const float*)d_in[2];
    const float* w_proj     = (const float*)d_in[3];
    const float* b_proj     = (const float*)d_in[4];
    const float* bias_table = (const float*)d_in[5];
    float* out = (float*)d_out;

    float *qkv, *att;
    cudaGetSymbolAddress((void**)&qkv, g_qkv);
    cudaGetSymbolAddress((void**)&att, g_att);

    const int M = B_SZ * N_TOK;  // 100352

    const size_t GEMM_SMEM = (size_t)
        ((STAGES * STAGE_SZ > BM * CSTR) ? STAGES * STAGE_SZ : BM * CSTR) * sizeof(float); // 67584 B
    const size_t ATT_SMEM = (size_t)
        (208 * KV_STR * 2 + 32 * KV_STR * 3 + 32 * SB_STR + 736) * sizeof(float); // 169856 B

    cudaFuncSetAttribute(gemm_bias_kernel, cudaFuncAttributeMaxDynamicSharedMemorySize,
                         (int)GEMM_SMEM);
    cudaFuncSetAttribute(attn_kernel, cudaFuncAttributeMaxDynamicSharedMemorySize,
                         (int)ATT_SMEM);

    gemm_bias_kernel<<<dim3(M / BM, 1536 / BN), 256, GEMM_SMEM>>>(
        x, w_qkv, b_qkv, qkv, M, 1536, 512);

    attn_kernel<<<B_SZ * HEADS, 512, ATT_SMEM>>>(qkv, bias_table, att);

    gemm_bias_kernel<<<dim3(M / BM, 512 / BN), 256, GEMM_SMEM>>>(
        att, w_proj, b_proj, out, M, 512, 512);
}

// round 3
// speedup vs baseline: 3.5944x; 2.6773x over previous
#include <cuda_runtime.h>
#include <cuda_fp16.h>
#include <mma.h>

using namespace nvcuda;

#define B_SZ   512
#define N_TOK  196
#define HEADS  8
#define DH     64

// ---------------- scratch (no allocs allowed) ----------------
__device__ __half g_xh[(size_t)B_SZ * N_TOK * 512];     // 103 MB
__device__ __half g_qkvh[(size_t)B_SZ * N_TOK * 1536];  // 308 MB
__device__ __half g_atth[(size_t)B_SZ * N_TOK * 512];   // 103 MB
__device__ __half g_wqkvh[512 * 1536];
__device__ __half g_wprojh[512 * 512];

// ---------------- f32 -> f16 convert ----------------
__global__ void cvt_kernel(const float* __restrict__ src, __half* __restrict__ dst, int n8)
{
    int i = blockIdx.x * blockDim.x + threadIdx.x;
    if (i < n8) {
        float4 a = *(const float4*)(src + i * 8);
        float4 b = *(const float4*)(src + i * 8 + 4);
        __half2 h[4];
        h[0] = __floats2half2_rn(a.x, a.y);
        h[1] = __floats2half2_rn(a.z, a.w);
        h[2] = __floats2half2_rn(b.x, b.y);
        h[3] = __floats2half2_rn(b.z, b.w);
        *(uint4*)(dst + i * 8) = *(uint4*)h;
    }
}

// ---------------- cp.async helpers ----------------
__device__ __forceinline__ void cp_async16(void* smem, const void* gmem) {
    unsigned s = (unsigned)__cvta_generic_to_shared(smem);
    asm volatile("cp.async.cg.shared.global [%0], [%1], 16;\n" :: "r"(s), "l"(gmem));
}
__device__ __forceinline__ void cp_commit() { asm volatile("cp.async.commit_group;\n"); }
template<int N> __device__ __forceinline__ void cp_wait() {
    asm volatile("cp.async.wait_group %0;\n" :: "n"(N));
}

// ---------------- fp16 GEMM + bias, 3-stage cp.async pipeline ----------------
// C[M,N] = A[M,K] @ W[K,N] + bias ; tiles 128x128x32 ; f32 accum
#define BM 128
#define BN 128
#define BK 32
#define STAGES 3
#define ASTR 40    // halves: 32 + 8 pad
#define BSTR 136   // halves: 128 + 8 pad
#define CSTR 132   // floats: 128 + 4 pad
#define AS_SZ (BM * ASTR)   // halves
#define BS_SZ (BK * BSTR)
#define STAGE_SZ (AS_SZ + BS_SZ)

__global__ void __launch_bounds__(256) gemm_bias_kernel(
    const __half* __restrict__ A, const __half* __restrict__ W,
    const float* __restrict__ bias, float* __restrict__ Cf, __half* __restrict__ Ch,
    int M, int Nn, int K, int outHalf)
{
    extern __shared__ char smraw[];
    __half* smh = (__half*)smraw;
    float*  Cs  = (float*)smraw;

    const int tid  = threadIdx.x;
    const int warp = tid >> 5;
    const int wm   = warp >> 2;     // 0..1 (64 rows)
    const int wn   = warp & 3;      // 0..3 (32 cols)
    const size_t m0 = (size_t)blockIdx.x * BM;
    const int    n0 = blockIdx.y * BN;

    const int ar = tid >> 2,  ach = (tid & 3) * 8;     // A: 64 rows/pass, 8 halves
    const int br = tid >> 4,  bch = (tid & 15) * 8;    // B: 16 rows/pass

    auto load_tile = [&](int stage, int kt) {
        __half* As = smh + stage * STAGE_SZ;
        __half* Bs = As + AS_SZ;
        int k0 = kt * BK;
        cp_async16(&As[ar * ASTR + ach],        &A[(m0 + ar) * K + k0 + ach]);
        cp_async16(&As[(ar + 64) * ASTR + ach], &A[(m0 + ar + 64) * K + k0 + ach]);
        cp_async16(&Bs[br * BSTR + bch],        &W[(size_t)(k0 + br) * Nn + n0 + bch]);
        cp_async16(&Bs[(br + 16) * BSTR + bch], &W[(size_t)(k0 + br + 16) * Nn + n0 + bch]);
        cp_commit();
    };

    wmma::fragment<wmma::accumulator, 16, 16, 16, float> acc[4][2];
#pragma unroll
    for (int i = 0; i < 4; i++)
#pragma unroll
        for (int j = 0; j < 2; j++) wmma::fill_fragment(acc[i][j], 0.f);

    const int KT = K / BK;
#pragma unroll
    for (int s = 0; s < STAGES - 1; s++) load_tile(s, s);

    for (int kt = 0; kt < KT; kt++) {
        if (kt <= KT - STAGES) cp_wait<STAGES - 2>(); else cp_wait<0>();
        __syncthreads();

        __half* As = smh + (kt % STAGES) * STAGE_SZ;
        __half* Bs = As + AS_SZ;
#pragma unroll
        for (int kk = 0; kk < BK; kk += 16) {
            wmma::fragment<wmma::matrix_a, 16, 16, 16, __half, wmma::row_major> af[4];
            wmma::fragment<wmma::matrix_b, 16, 16, 16, __half, wmma::row_major> bf[2];
#pragma unroll
            for (int i = 0; i < 4; i++)
                wmma::load_matrix_sync(af[i], &As[(wm * 64 + i * 16) * ASTR + kk], ASTR);
#pragma unroll
            for (int j = 0; j < 2; j++)
                wmma::load_matrix_sync(bf[j], &Bs[kk * BSTR + wn * 32 + j * 16], BSTR);
#pragma unroll
            for (int i = 0; i < 4; i++)
#pragma unroll
                for (int j = 0; j < 2; j++)
                    wmma::mma_sync(acc[i][j], af[i], bf[j], acc[i][j]);
        }
        __syncthreads();

        int nt = kt + STAGES - 1;
        if (nt < KT) load_tile(nt % STAGES, nt);
    }

#pragma unroll
    for (int i = 0; i < 4; i++)
#pragma unroll
        for (int j = 0; j < 2; j++)
            wmma::store_matrix_sync(&Cs[(wm * 64 + i * 16) * CSTR + wn * 32 + j * 16],
                                    acc[i][j], CSTR, wmma::mem_row_major);
    __syncthreads();

    const int cr = tid >> 4, cc = (tid & 15) * 8;
    float4 bv0 = *(const float4*)&bias[n0 + cc];
    float4 bv1 = *(const float4*)&bias[n0 + cc + 4];
#pragma unroll
    for (int it = 0; it < 8; it++) {
        int r = cr + it * 16;
        float4 v0 = *(float4*)&Cs[r * CSTR + cc];
        float4 v1 = *(float4*)&Cs[r * CSTR + cc + 4];
        v0.x += bv0.x; v0.y += bv0.y; v0.z += bv0.z; v0.w += bv0.w;
        v1.x += bv1.x; v1.y += bv1.y; v1.z += bv1.z; v1.w += bv1.w;
        if (outHalf) {
            __half2 h[4];
            h[0] = __floats2half2_rn(v0.x, v0.y);
            h[1] = __floats2half2_rn(v0.z, v0.w);
            h[2] = __floats2half2_rn(v1.x, v1.y);
            h[3] = __floats2half2_rn(v1.z, v1.w);
            *(uint4*)&Ch[(m0 + r) * Nn + n0 + cc] = *(uint4*)h;
        } else {
            *(float4*)&Cf[(m0 + r) * Nn + n0 + cc] = v0;
            *(float4*)&Cf[(m0 + r) * Nn + n0 + cc + 4] = v1;
        }
    }
}

// ---------------- fused window attention (fp16 operands, f32 softmax) ----------------
// one CTA per (b, h), 512 threads, 64-row bands
#define KVSTR 72    // halves
#define SBSTR 216   // floats
#define PSTR  224   // halves

// smem offsets in bytes
#define OFF_KS   0
#define OFF_VS   (OFF_KS + 208 * KVSTR * 2)         // 29952
#define OFF_QO   (OFF_VS + 208 * KVSTR * 2)         // union: Qb half 64x72 / Ob f32 64x68
#define OFF_SB   (OFF_QO + 64 * 68 * 4)             // 17408
#define OFF_PB   (OFF_SB + 64 * SBSTR * 4)          // 55296
#define OFF_BIAS (OFF_PB + 64 * PSTR * 2)           // 28672
#define OFF_JQR  (OFF_BIAS + 736 * 4)
#define ATT_SMEM (OFF_JQR + 208 * 4)

__global__ void __launch_bounds__(512) attn_kernel(
    const __half* __restrict__ qkv, const float* __restrict__ bias_table,
    __half* __restrict__ att)
{
    extern __shared__ char smraw[];
    __half* Ks    = (__half*)(smraw + OFF_KS);
    __half* Vs    = (__half*)(smraw + OFF_VS);
    __half* Qb    = (__half*)(smraw + OFF_QO);
    float*  Ob    = (float*)(smraw + OFF_QO);
    float*  Sb    = (float*)(smraw + OFF_SB);
    __half* Pb    = (__half*)(smraw + OFF_PB);
    float*  biasS = (float*)(smraw + OFF_BIAS);
    int*    jqr   = (int*)(smraw + OFF_JQR);

    const int tid  = threadIdx.x;
    const int lane = tid & 31;
    const int warp = tid >> 5;               // 0..15
    const int b = blockIdx.x >> 3;
    const int h = blockIdx.x & 7;

    const __half* base = qkv + (size_t)b * N_TOK * 1536 + h * DH;

    // ---- K, V -> smem ----
    for (int idx = tid; idx < N_TOK * 8; idx += 512) {
        int r = idx >> 3, c8 = (idx & 7) * 8;
        const __half* rp = base + (size_t)r * 1536;
        *(uint4*)&Ks[r * KVSTR + c8] = *(const uint4*)(rp + 512 + c8);
        *(uint4*)&Vs[r * KVSTR + c8] = *(const uint4*)(rp + 1024 + c8);
    }
    for (int idx = tid; idx < 12 * 9; idx += 512) {       // zero pad rows 196..207 (72 cols)
        int r = 196 + idx / 9, c8 = (idx % 9) * 8;
        uint4 z = make_uint4(0, 0, 0, 0);
        *(uint4*)&Ks[r * KVSTR + c8] = z;
        *(uint4*)&Vs[r * KVSTR + c8] = z;
    }
    for (int t = tid; t < 729; t += 512) biasS[t] = bias_table[t * HEADS + h];
    for (int j = tid; j < 196; j += 512) {
        int jq = j / 14;
        jqr[j] = jq * 27 + (j - jq * 14);
    }
    __syncthreads();

    const __half2 qs2 = __floats2half2_rn(0.125f, 0.125f);

    for (int ib = 0; ib < 4; ib++) {
        const int i0 = ib * 64;

        // ---- Q band (scaled by 0.125, exact in fp16) ----
        {
            int r = tid >> 3, c8 = (tid & 7) * 8;
            int i = i0 + r;
            uint4 q = make_uint4(0, 0, 0, 0);
            if (i < N_TOK) {
                q = *(const uint4*)(base + (size_t)i * 1536 + c8);
                __half2* qh = (__half2*)&q;
#pragma unroll
                for (int t = 0; t < 4; t++) qh[t] = __hmul2(qh[t], qs2);
            }
            *(uint4*)&Qb[r * KVSTR + c8] = q;
        }
        __syncthreads();

        // ---- scores: S[64][208] = Qb @ Ks^T ; 52 tiles over 16 warps ----
        for (int t = warp; t < 52; t += 16) {
            int tm = t / 13, tj = t - tm * 13;
            if (i0 + tm * 16 < N_TOK) {
                wmma::fragment<wmma::accumulator, 16, 16, 16, float> acc;
                wmma::fill_fragment(acc, 0.f);
#pragma unroll
                for (int kk = 0; kk < DH; kk += 16) {
                    wmma::fragment<wmma::matrix_a, 16, 16, 16, __half, wmma::row_major> af;
                    wmma::fragment<wmma::matrix_b, 16, 16, 16, __half, wmma::col_major> bf;
                    wmma::load_matrix_sync(af, &Qb[tm * 16 * KVSTR + kk], KVSTR);
                    wmma::load_matrix_sync(bf, &Ks[tj * 16 * KVSTR + kk], KVSTR);
                    wmma::mma_sync(acc, af, bf, acc);
                }
                wmma::store_matrix_sync(&Sb[tm * 16 * SBSTR + tj * 16], acc, SBSTR,
                                        wmma::mem_row_major);
            }
        }
        __syncthreads();

        // ---- softmax + rel-pos bias : 4 rows per warp ----
#pragma unroll
        for (int rr = 0; rr < 4; rr++) {
            int r = warp + rr * 16;
            int i = i0 + r;
            float*  srow = &Sb[r * SBSTR];
            __half* prow = &Pb[r * PSTR];
            if (i < N_TOK) {
                int ibase = (i / 14) * 27 + (i % 14) + 364;   // 13*28
                float mx = -1e30f;
                for (int j = lane; j < N_TOK; j += 32) {
                    float t = srow[j] + biasS[ibase - jqr[j]];
                    srow[j] = t;
                    mx = fmaxf(mx, t);
                }
#pragma unroll
                for (int o = 16; o > 0; o >>= 1) mx = fmaxf(mx, __shfl_xor_sync(0xffffffffu, mx, o));
                float sum = 0.f;
                for (int j = lane; j < N_TOK; j += 32) {
                    float p = __expf(srow[j] - mx);
                    srow[j] = p;
                    sum += p;
                }
#pragma unroll
                for (int o = 16; o > 0; o >>= 1) sum += __shfl_xor_sync(0xffffffffu, sum, o);
                float rinv = __frcp_rn(sum);
                for (int j = lane; j < N_TOK; j += 32)
                    prow[j] = __float2half_rn(srow[j] * rinv);
                if (lane < 12) prow[196 + lane] = __ushort_as_half(0);
            } else {
                for (int j = lane; j < 208; j += 32) prow[j] = __ushort_as_half(0);
            }
        }
        __syncthreads();

        // ---- O = P @ V : 16 tiles, one per warp, k=208 ----
        {
            int tm = warp >> 2, tn = warp & 3;
            if (i0 + tm * 16 < N_TOK) {
                wmma::fragment<wmma::accumulator, 16, 16, 16, float> oacc;
                wmma::fill_fragment(oacc, 0.f);
#pragma unroll
                for (int ks = 0; ks < 13; ks++) {
                    int k16 = ks * 16;
                    wmma::fragment<wmma::matrix_a, 16, 16, 16, __half, wmma::row_major> af;
                    wmma::fragment<wmma::matrix_b, 16, 16, 16, __half, wmma::row_major> bf;
                    wmma::load_matrix_sync(af, &Pb[tm * 16 * PSTR + k16], PSTR);
                    wmma::load_matrix_sync(bf, &Vs[k16 * KVSTR + tn * 16], KVSTR);
                    wmma::mma_sync(oacc, af, bf, oacc);
                }
                wmma::store_matrix_sync(&Ob[tm * 16 * 68 + tn * 16], oacc, 68,
                                        wmma::mem_row_major);
            }
        }
        __syncthreads();

        // ---- writeback O as half ----
        {
            int r = tid >> 3, c8 = (tid & 7) * 8;
            int i = i0 + r;
            if (i < N_TOK) {
                float4 v0 = *(float4*)&Ob[r * 68 + c8];
                float4 v1 = *(float4*)&Ob[r * 68 + c8 + 4];
                __half2 hh[4];
                hh[0] = __floats2half2_rn(v0.x, v0.y);
                hh[1] = __floats2half2_rn(v0.z, v0.w);
                hh[2] = __floats2half2_rn(v1.x, v1.y);
                hh[3] = __floats2half2_rn(v1.z, v1.w);
                *(uint4*)&att[(size_t)(b * N_TOK + i) * 512 + h * DH + c8] = *(uint4*)hh;
            }
        }
        __syncthreads();
    }
}

// ---------------- launcher ----------------
extern "C" void kernel_launch(void* const* d_in, const int* in_sizes, int n_in,
                              void* d_out, int out_size)
{
    const float* x          = (const float*)d_in[0];
    const float* w_qkv      = (const float*)d_in[1];
    const float* b_qkv      = (const float*)d_in[2];
    const float* w_proj     = (const float*)d_in[3];
    const float* b_proj     = (const float*)d_in[4];
    const float* bias_table = (const float*)d_in[5];
    float* out = (float*)d_out;

    __half *xh, *qkvh, *atth, *wqkvh, *wprojh;
    cudaGetSymbolAddress((void**)&xh,     g_xh);
    cudaGetSymbolAddress((void**)&qkvh,   g_qkvh);
    cudaGetSymbolAddress((void**)&atth,   g_atth);
    cudaGetSymbolAddress((void**)&wqkvh,  g_wqkvh);
    cudaGetSymbolAddress((void**)&wprojh, g_wprojh);

    const int M = B_SZ * N_TOK;  // 100352

    const size_t GEMM_SMEM = 128 * CSTR * sizeof(float) > (size_t)STAGES * STAGE_SZ * 2
                           ? 128 * CSTR * sizeof(float) : (size_t)STAGES * STAGE_SZ * 2;

    cudaFuncSetAttribute(gemm_bias_kernel, cudaFuncAttributeMaxDynamicSharedMemorySize,
                         (int)GEMM_SMEM);
    cudaFuncSetAttribute(attn_kernel, cudaFuncAttributeMaxDynamicSharedMemorySize,
                         (int)ATT_SMEM);

    { int n8 = M * 512 / 8;    cvt_kernel<<<(n8 + 255) / 256, 256>>>(x, xh, n8); }
    { int n8 = 512 * 1536 / 8; cvt_kernel<<<(n8 + 255) / 256, 256>>>(w_qkv, wqkvh, n8); }
    { int n8 = 512 * 512 / 8;  cvt_kernel<<<(n8 + 255) / 256, 256>>>(w_proj, wprojh, n8); }

    gemm_bias_kernel<<<dim3(M / BM, 1536 / BN), 256, GEMM_SMEM>>>(
        xh, wqkvh, b_qkv, nullptr, qkvh, M, 1536, 512, 1);

    attn_kernel<<<B_SZ * HEADS, 512, ATT_SMEM>>>(qkvh, bias_table, atth);

    gemm_bias_kernel<<<dim3(M / BM, 512 / BN), 256, GEMM_SMEM>>>(
        atth, wprojh, b_proj, out, nullptr, M, 512, 512, 0);
}

// round 4
// speedup vs baseline: 4.5210x; 1.2578x over previous
#include <cuda_runtime.h>
#include <cuda_fp16.h>
#include <mma.h>

using namespace nvcuda;

#define B_SZ   512
#define N_TOK  196
#define HEADS  8
#define DH     64

// ---------------- scratch (no allocs allowed) ----------------
__device__ __half g_xh[(size_t)B_SZ * N_TOK * 512];     // 103 MB
__device__ __half g_qkvh[(size_t)B_SZ * N_TOK * 1536];  // 308 MB
__device__ __half g_atth[(size_t)B_SZ * N_TOK * 512];   // 103 MB
__device__ __half g_wqkvh[512 * 1536];
__device__ __half g_wprojh[512 * 512];

// ---------------- f32 -> f16 convert ----------------
__global__ void cvt_kernel(const float* __restrict__ src, __half* __restrict__ dst, int n8)
{
    int i = blockIdx.x * blockDim.x + threadIdx.x;
    if (i < n8) {
        float4 a = *(const float4*)(src + i * 8);
        float4 b = *(const float4*)(src + i * 8 + 4);
        __half2 h[4];
        h[0] = __floats2half2_rn(a.x, a.y);
        h[1] = __floats2half2_rn(a.z, a.w);
        h[2] = __floats2half2_rn(b.x, b.y);
        h[3] = __floats2half2_rn(b.z, b.w);
        *(uint4*)(dst + i * 8) = *(uint4*)h;
    }
}

// ---------------- cp.async helpers ----------------
__device__ __forceinline__ void cp_async16(void* smem, const void* gmem) {
    unsigned s = (unsigned)__cvta_generic_to_shared(smem);
    asm volatile("cp.async.cg.shared.global [%0], [%1], 16;\n" :: "r"(s), "l"(gmem));
}
__device__ __forceinline__ void cp_commit() { asm volatile("cp.async.commit_group;\n"); }
template<int N> __device__ __forceinline__ void cp_wait() {
    asm volatile("cp.async.wait_group %0;\n" :: "n"(N));
}

// ---------------- fp16 GEMM + bias, 4-stage cp.async pipeline, 1 sync/iter ----------------
// C[M,N] = A[M,K] @ W[K,N] + bias ; tiles 128x128x32 ; f32 accum
#define BM 128
#define BN 128
#define BK 32
#define STAGES 4
#define ASTR 40    // halves: 32 + 8 pad
#define BSTR 136   // halves: 128 + 8 pad
#define CSTR 132   // floats: 128 + 4 pad
#define AS_SZ (BM * ASTR)
#define BS_SZ (BK * BSTR)
#define STAGE_SZ (AS_SZ + BS_SZ)

__global__ void __launch_bounds__(256) gemm_bias_kernel(
    const __half* __restrict__ A, const __half* __restrict__ W,
    const float* __restrict__ bias, float* __restrict__ Cf, __half* __restrict__ Ch,
    int M, int Nn, int K, int outHalf)
{
    extern __shared__ char smraw[];
    __half* smh = (__half*)smraw;
    float*  Cs  = (float*)smraw;

    const int tid  = threadIdx.x;
    const int warp = tid >> 5;
    const int wm   = warp >> 2;     // 0..1 (64 rows)
    const int wn   = warp & 3;      // 0..3 (32 cols)
    const size_t m0 = (size_t)blockIdx.y * BM;   // n fastest -> A-tile reuse in L2
    const int    n0 = blockIdx.x * BN;

    const int ar = tid >> 2,  ach = (tid & 3) * 8;
    const int br = tid >> 4,  bch = (tid & 15) * 8;

    auto load_tile = [&](int stage, int kt) {
        __half* As = smh + stage * STAGE_SZ;
        __half* Bs = As + AS_SZ;
        int k0 = kt * BK;
        cp_async16(&As[ar * ASTR + ach],        &A[(m0 + ar) * K + k0 + ach]);
        cp_async16(&As[(ar + 64) * ASTR + ach], &A[(m0 + ar + 64) * K + k0 + ach]);
        cp_async16(&Bs[br * BSTR + bch],        &W[(size_t)(k0 + br) * Nn + n0 + bch]);
        cp_async16(&Bs[(br + 16) * BSTR + bch], &W[(size_t)(k0 + br + 16) * Nn + n0 + bch]);
        cp_commit();
    };

    wmma::fragment<wmma::accumulator, 16, 16, 16, float> acc[4][2];
#pragma unroll
    for (int i = 0; i < 4; i++)
#pragma unroll
        for (int j = 0; j < 2; j++) wmma::fill_fragment(acc[i][j], 0.f);

    const int KT = K / BK;
#pragma unroll
    for (int s = 0; s < STAGES - 1; s++) load_tile(s, s);

    for (int kt = 0; kt < KT; kt++) {
        if (kt <= KT - STAGES) cp_wait<STAGES - 2>(); else cp_wait<0>();
        __syncthreads();
        // issue next load BEFORE compute: target stage (kt+3)%4 was last read at
        // iter kt-1, and every thread past this barrier has finished iter kt-1.
        int nt = kt + STAGES - 1;
        if (nt < KT) load_tile(nt % STAGES, nt);

        __half* As = smh + (kt % STAGES) * STAGE_SZ;
        __half* Bs = As + AS_SZ;
#pragma unroll
        for (int kk = 0; kk < BK; kk += 16) {
            wmma::fragment<wmma::matrix_a, 16, 16, 16, __half, wmma::row_major> af[4];
            wmma::fragment<wmma::matrix_b, 16, 16, 16, __half, wmma::row_major> bf[2];
#pragma unroll
            for (int i = 0; i < 4; i++)
                wmma::load_matrix_sync(af[i], &As[(wm * 64 + i * 16) * ASTR + kk], ASTR);
#pragma unroll
            for (int j = 0; j < 2; j++)
                wmma::load_matrix_sync(bf[j], &Bs[kk * BSTR + wn * 32 + j * 16], BSTR);
#pragma unroll
            for (int i = 0; i < 4; i++)
#pragma unroll
                for (int j = 0; j < 2; j++)
                    wmma::mma_sync(acc[i][j], af[i], bf[j], acc[i][j]);
        }
    }
    __syncthreads();   // before reusing smem for epilogue

#pragma unroll
    for (int i = 0; i < 4; i++)
#pragma unroll
        for (int j = 0; j < 2; j++)
            wmma::store_matrix_sync(&Cs[(wm * 64 + i * 16) * CSTR + wn * 32 + j * 16],
                                    acc[i][j], CSTR, wmma::mem_row_major);
    __syncthreads();

    const int cr = tid >> 4, cc = (tid & 15) * 8;
    float4 bv0 = *(const float4*)&bias[n0 + cc];
    float4 bv1 = *(const float4*)&bias[n0 + cc + 4];
#pragma unroll
    for (int it = 0; it < 8; it++) {
        int r = cr + it * 16;
        float4 v0 = *(float4*)&Cs[r * CSTR + cc];
        float4 v1 = *(float4*)&Cs[r * CSTR + cc + 4];
        v0.x += bv0.x; v0.y += bv0.y; v0.z += bv0.z; v0.w += bv0.w;
        v1.x += bv1.x; v1.y += bv1.y; v1.z += bv1.z; v1.w += bv1.w;
        if (outHalf) {
            __half2 h[4];
            h[0] = __floats2half2_rn(v0.x, v0.y);
            h[1] = __floats2half2_rn(v0.z, v0.w);
            h[2] = __floats2half2_rn(v1.x, v1.y);
            h[3] = __floats2half2_rn(v1.z, v1.w);
            *(uint4*)&Ch[(m0 + r) * Nn + n0 + cc] = *(uint4*)h;
        } else {
            *(float4*)&Cf[(m0 + r) * Nn + n0 + cc] = v0;
            *(float4*)&Cf[(m0 + r) * Nn + n0 + cc + 4] = v1;
        }
    }
}

// ---------------- fused window attention: 32-row bands, 113 KB smem -> 2 CTAs/SM ----------------
#define KVSTR 72    // halves
#define SBSTR 212   // floats
#define PSTR  216   // halves

// smem offsets in bytes (aliasing: Ob0<->Qb, Ob1<->Sb; both dead post-softmax)
#define OFF_KS   0                              // 208*72*2 = 29952
#define OFF_VS   (OFF_KS + 208 * KVSTR * 2)     // 29952
#define OFF_QO   (OFF_VS + 208 * KVSTR * 2)     // max(Qb 4608, Ob0 8704) = 8704
#define OFF_SB   (OFF_QO + 32 * 68 * 4)         // max(Sb 27136, Ob1 8704) = 27136
#define OFF_PB   (OFF_SB + 32 * SBSTR * 4)      // 32*216*2 = 13824
#define OFF_BIAS (OFF_PB + 32 * PSTR * 2)       // 736*4
#define OFF_JQR  (OFF_BIAS + 736 * 4)           // 208*4
#define ATT_SMEM (OFF_JQR + 208 * 4)            // = 113344 B

__global__ void __launch_bounds__(512) attn_kernel(
    const __half* __restrict__ qkv, const float* __restrict__ bias_table,
    __half* __restrict__ att)
{
    extern __shared__ char smraw[];
    __half* Ks    = (__half*)(smraw + OFF_KS);
    __half* Vs    = (__half*)(smraw + OFF_VS);
    __half* Qb    = (__half*)(smraw + OFF_QO);
    float*  Ob0   = (float*)(smraw + OFF_QO);
    float*  Sb    = (float*)(smraw + OFF_SB);
    float*  Ob1   = (float*)(smraw + OFF_SB);
    __half* Pb    = (__half*)(smraw + OFF_PB);
    float*  biasS = (float*)(smraw + OFF_BIAS);
    int*    jqr   = (int*)(smraw + OFF_JQR);

    const int tid  = threadIdx.x;
    const int lane = tid & 31;
    const int warp = tid >> 5;               // 0..15
    const int b = blockIdx.x >> 3;
    const int h = blockIdx.x & 7;

    const __half* base = qkv + (size_t)b * N_TOK * 1536 + h * DH;

    // ---- K, V -> smem ----
    for (int idx = tid; idx < N_TOK * 8; idx += 512) {
        int r = idx >> 3, c8 = (idx & 7) * 8;
        const __half* rp = base + (size_t)r * 1536;
        *(uint4*)&Ks[r * KVSTR + c8] = *(const uint4*)(rp + 512 + c8);
        *(uint4*)&Vs[r * KVSTR + c8] = *(const uint4*)(rp + 1024 + c8);
    }
    for (int idx = tid; idx < 12 * 9; idx += 512) {    // zero rows 196..207 incl. pad cols
        int r = 196 + idx / 9, c8 = (idx % 9) * 8;
        uint4 z = make_uint4(0, 0, 0, 0);
        *(uint4*)&Ks[r * KVSTR + c8] = z;
        *(uint4*)&Vs[r * KVSTR + c8] = z;
    }
    for (int t = tid; t < 729; t += 512) biasS[t] = bias_table[t * HEADS + h];
    for (int j = tid; j < 196; j += 512) {
        int jq = j / 14;
        jqr[j] = jq * 27 + (j - jq * 14);
    }
    __syncthreads();

    const __half2 qs2 = __floats2half2_rn(0.125f, 0.125f);

    for (int ib = 0; ib < 7; ib++) {
        const int i0 = ib * 32;

        // ---- Q band 32x64 (scaled; 0.125 exact in fp16): 256 uint4 over 512 thr ----
        if (tid < 256) {
            int r = tid >> 3, c8 = (tid & 7) * 8;
            int i = i0 + r;
            uint4 q = make_uint4(0, 0, 0, 0);
            if (i < N_TOK) {
                q = *(const uint4*)(base + (size_t)i * 1536 + c8);
                __half2* qh = (__half2*)&q;
#pragma unroll
                for (int t = 0; t < 4; t++) qh[t] = __hmul2(qh[t], qs2);
            }
            *(uint4*)&Qb[r * KVSTR + c8] = q;
        }
        __syncthreads();

        // ---- scores: S[32][208] = Qb @ Ks^T ; 26 tiles over 16 warps ----
        for (int t = warp; t < 26; t += 16) {
            int tm = t / 13, tj = t - tm * 13;
            if (i0 + tm * 16 < N_TOK) {
                wmma::fragment<wmma::accumulator, 16, 16, 16, float> acc;
                wmma::fill_fragment(acc, 0.f);
#pragma unroll
                for (int kk = 0; kk < DH; kk += 16) {
                    wmma::fragment<wmma::matrix_a, 16, 16, 16, __half, wmma::row_major> af;
                    wmma::fragment<wmma::matrix_b, 16, 16, 16, __half, wmma::col_major> bf;
                    wmma::load_matrix_sync(af, &Qb[tm * 16 * KVSTR + kk], KVSTR);
                    wmma::load_matrix_sync(bf, &Ks[tj * 16 * KVSTR + kk], KVSTR);
                    wmma::mma_sync(acc, af, bf, acc);
                }
                wmma::store_matrix_sync(&Sb[tm * 16 * SBSTR + tj * 16], acc, SBSTR,
                                        wmma::mem_row_major);
            }
        }
        __syncthreads();

        // ---- softmax + rel-pos bias : 2 rows per warp ----
#pragma unroll
        for (int rr = 0; rr < 2; rr++) {
            int r = warp * 2 + rr;
            int i = i0 + r;
            float*  srow = &Sb[r * SBSTR];
            __half* prow = &Pb[r * PSTR];
            if (i < N_TOK) {
                int ibase = (i / 14) * 27 + (i % 14) + 364;
                float mx = -1e30f;
                for (int j = lane; j < N_TOK; j += 32) {
                    float t = srow[j] + biasS[ibase - jqr[j]];
                    srow[j] = t;
                    mx = fmaxf(mx, t);
                }
#pragma unroll
                for (int o = 16; o > 0; o >>= 1) mx = fmaxf(mx, __shfl_xor_sync(0xffffffffu, mx, o));
                float sum = 0.f;
                for (int j = lane; j < N_TOK; j += 32) {
                    float p = __expf(srow[j] - mx);
                    srow[j] = p;
                    sum += p;
                }
#pragma unroll
                for (int o = 16; o > 0; o >>= 1) sum += __shfl_xor_sync(0xffffffffu, sum, o);
                float rinv = __frcp_rn(sum);
                for (int j = lane; j < N_TOK; j += 32)
                    prow[j] = __float2half_rn(srow[j] * rinv);
                if (lane < 12) prow[196 + lane] = __ushort_as_half(0);
            } else {
                for (int j = lane; j < 208; j += 32) prow[j] = __ushort_as_half(0);
            }
        }
        __syncthreads();

        // ---- O = P @ V : 8 tiles x k-split 2 = 16 warps (Ob0/Ob1 alias Qb/Sb) ----
        {
            int tile = warp >> 1, half = warp & 1;
            int tm = tile >> 2, tn = tile & 3;
            if (i0 + tm * 16 < N_TOK) {
                wmma::fragment<wmma::accumulator, 16, 16, 16, float> oacc;
                wmma::fill_fragment(oacc, 0.f);
                int s0 = half ? 7 : 0, s1 = half ? 13 : 7;
                for (int ks = s0; ks < s1; ks++) {
                    int k16 = ks * 16;
                    wmma::fragment<wmma::matrix_a, 16, 16, 16, __half, wmma::row_major> af;
                    wmma::fragment<wmma::matrix_b, 16, 16, 16, __half, wmma::row_major> bf;
                    wmma::load_matrix_sync(af, &Pb[tm * 16 * PSTR + k16], PSTR);
                    wmma::load_matrix_sync(bf, &Vs[k16 * KVSTR + tn * 16], KVSTR);
                    wmma::mma_sync(oacc, af, bf, oacc);
                }
                float* Ob = half ? Ob1 : Ob0;
                wmma::store_matrix_sync(&Ob[tm * 16 * 68 + tn * 16], oacc, 68,
                                        wmma::mem_row_major);
            }
        }
        __syncthreads();

        // ---- writeback: merge halves, cast to half ----
        if (tid < 256) {
            int r = tid >> 3, c8 = (tid & 7) * 8;
            int i = i0 + r;
            if (i < N_TOK) {
                float4 a0 = *(float4*)&Ob0[r * 68 + c8];
                float4 a1 = *(float4*)&Ob0[r * 68 + c8 + 4];
                float4 b0 = *(float4*)&Ob1[r * 68 + c8];
                float4 b1 = *(float4*)&Ob1[r * 68 + c8 + 4];
                __half2 hh[4];
                hh[0] = __floats2half2_rn(a0.x + b0.x, a0.y + b0.y);
                hh[1] = __floats2half2_rn(a0.z + b0.z, a0.w + b0.w);
                hh[2] = __floats2half2_rn(a1.x + b1.x, a1.y + b1.y);
                hh[3] = __floats2half2_rn(a1.z + b1.z, a1.w + b1.w);
                *(uint4*)&att[(size_t)(b * N_TOK + i) * 512 + h * DH + c8] = *(uint4*)hh;
            }
        }
        __syncthreads();
    }
}

// ---------------- launcher ----------------
extern "C" void kernel_launch(void* const* d_in, const int* in_sizes, int n_in,
                              void* d_out, int out_size)
{
    const float* x          = (const float*)d_in[0];
    const float* w_qkv      = (const float*)d_in[1];
    const float* b_qkv      = (const float*)d_in[2];
    const float* w_proj     = (const float*)d_in[3];
    const float* b_proj     = (const float*)d_in[4];
    const float* bias_table = (const float*)d_in[5];
    float* out = (float*)d_out;

    __half *xh, *qkvh, *atth, *wqkvh, *wprojh;
    cudaGetSymbolAddress((void**)&xh,     g_xh);
    cudaGetSymbolAddress((void**)&qkvh,   g_qkvh);
    cudaGetSymbolAddress((void**)&atth,   g_atth);
    cudaGetSymbolAddress((void**)&wqkvh,  g_wqkvh);
    cudaGetSymbolAddress((void**)&wprojh, g_wprojh);

    const int M = B_SZ * N_TOK;  // 100352

    const size_t PIPE_B = (size_t)STAGES * STAGE_SZ * 2;      // 75776
    const size_t EPI_B  = (size_t)BM * CSTR * 4;              // 67584
    const size_t GEMM_SMEM = PIPE_B > EPI_B ? PIPE_B : EPI_B;

    cudaFuncSetAttribute(gemm_bias_kernel, cudaFuncAttributeMaxDynamicSharedMemorySize,
                         (int)GEMM_SMEM);
    cudaFuncSetAttribute(attn_kernel, cudaFuncAttributeMaxDynamicSharedMemorySize,
                         (int)ATT_SMEM);

    { int n8 = M * 512 / 8;    cvt_kernel<<<(n8 + 255) / 256, 256>>>(x, xh, n8); }
    { int n8 = 512 * 1536 / 8; cvt_kernel<<<(n8 + 255) / 256, 256>>>(w_qkv, wqkvh, n8); }
    { int n8 = 512 * 512 / 8;  cvt_kernel<<<(n8 + 255) / 256, 256>>>(w_proj, wprojh, n8); }

    gemm_bias_kernel<<<dim3(1536 / BN, M / BM), 256, GEMM_SMEM>>>(
        xh, wqkvh, b_qkv, nullptr, qkvh, M, 1536, 512, 1);

    attn_kernel<<<B_SZ * HEADS, 512, ATT_SMEM>>>(qkvh, bias_table, atth);

    gemm_bias_kernel<<<dim3(512 / BN, M / BM), 256, GEMM_SMEM>>>(
        atth, wprojh, b_proj, out, nullptr, M, 512, 512, 0);
}

// round 8
// speedup vs baseline: 5.8237x; 1.2881x over previous
#include <cuda_runtime.h>
#include <cuda_fp16.h>
#include <mma.h>

using namespace nvcuda;

#define B_SZ   512
#define N_TOK  196
#define HEADS  8
#define DH     64

// ---------------- scratch (no allocs allowed) ----------------
__device__ __half g_xh[(size_t)B_SZ * N_TOK * 512];
__device__ __half g_qkvh[(size_t)B_SZ * N_TOK * 1536];
__device__ __half g_atth[(size_t)B_SZ * N_TOK * 512];
__device__ __half g_wqkvh[512 * 1536];
__device__ __half g_wprojh[512 * 512];

// ---------------- f32 -> f16 convert ----------------
__global__ void cvt_kernel(const float* __restrict__ src, __half* __restrict__ dst, int n8)
{
    int i = blockIdx.x * blockDim.x + threadIdx.x;
    if (i < n8) {
        float4 a = *(const float4*)(src + i * 8);
        float4 b = *(const float4*)(src + i * 8 + 4);
        __half2 h[4];
        h[0] = __floats2half2_rn(a.x, a.y);
        h[1] = __floats2half2_rn(a.z, a.w);
        h[2] = __floats2half2_rn(b.x, b.y);
        h[3] = __floats2half2_rn(b.z, b.w);
        *(uint4*)(dst + i * 8) = *(uint4*)h;
    }
}

// ---------------- cp.async helpers ----------------
__device__ __forceinline__ void cp_async16(void* smem, const void* gmem) {
    unsigned s = (unsigned)__cvta_generic_to_shared(smem);
    asm volatile("cp.async.cg.shared.global [%0], [%1], 16;\n" :: "r"(s), "l"(gmem));
}
__device__ __forceinline__ void cp_commit() { asm volatile("cp.async.commit_group;\n"); }
template<int N> __device__ __forceinline__ void cp_wait() {
    asm volatile("cp.async.wait_group %0;\n" :: "n"(N));
}

// ---------------- mma / ldmatrix helpers ----------------
__device__ __forceinline__ void ldsm_x2(unsigned& r0, unsigned& r1, unsigned addr) {
    asm volatile("ldmatrix.sync.aligned.m8n8.x2.shared.b16 {%0,%1}, [%2];\n"
                 : "=r"(r0), "=r"(r1) : "r"(addr));
}
__device__ __forceinline__ void ldsm_x2_t(unsigned& r0, unsigned& r1, unsigned addr) {
    asm volatile("ldmatrix.sync.aligned.m8n8.x2.trans.shared.b16 {%0,%1}, [%2];\n"
                 : "=r"(r0), "=r"(r1) : "r"(addr));
}
__device__ __forceinline__ void mma16816(float* c, const unsigned* a, unsigned b0, unsigned b1) {
    asm volatile("mma.sync.aligned.m16n8k16.row.col.f32.f16.f16.f32 "
                 "{%0,%1,%2,%3}, {%4,%5,%6,%7}, {%8,%9}, {%0,%1,%2,%3};\n"
                 : "+f"(c[0]), "+f"(c[1]), "+f"(c[2]), "+f"(c[3])
                 : "r"(a[0]), "r"(a[1]), "r"(a[2]), "r"(a[3]), "r"(b0), "r"(b1));
}

// ---------------- fp16 GEMM + bias, 4-stage cp.async pipeline ----------------
#define BM 128
#define BN 128
#define BK 32
#define STAGES 4
#define ASTR 40
#define BSTR 136
#define CSTR 132
#define AS_SZ (BM * ASTR)
#define BS_SZ (BK * BSTR)
#define STAGE_SZ (AS_SZ + BS_SZ)

__global__ void __launch_bounds__(256) gemm_bias_kernel(
    const __half* __restrict__ A, const __half* __restrict__ W,
    const float* __restrict__ bias, float* __restrict__ Cf, __half* __restrict__ Ch,
    int M, int Nn, int K, int outHalf)
{
    extern __shared__ char smraw[];
    __half* smh = (__half*)smraw;
    float*  Cs  = (float*)smraw;

    const int tid  = threadIdx.x;
    const int warp = tid >> 5;
    const int wm   = warp >> 2;
    const int wn   = warp & 3;
    const size_t m0 = (size_t)blockIdx.y * BM;
    const int    n0 = blockIdx.x * BN;

    const int ar = tid >> 2,  ach = (tid & 3) * 8;
    const int br = tid >> 4,  bch = (tid & 15) * 8;

    auto load_tile = [&](int stage, int kt) {
        __half* As = smh + stage * STAGE_SZ;
        __half* Bs = As + AS_SZ;
        int k0 = kt * BK;
        cp_async16(&As[ar * ASTR + ach],        &A[(m0 + ar) * K + k0 + ach]);
        cp_async16(&As[(ar + 64) * ASTR + ach], &A[(m0 + ar + 64) * K + k0 + ach]);
        cp_async16(&Bs[br * BSTR + bch],        &W[(size_t)(k0 + br) * Nn + n0 + bch]);
        cp_async16(&Bs[(br + 16) * BSTR + bch], &W[(size_t)(k0 + br + 16) * Nn + n0 + bch]);
        cp_commit();
    };

    wmma::fragment<wmma::accumulator, 16, 16, 16, float> acc[4][2];
#pragma unroll
    for (int i = 0; i < 4; i++)
#pragma unroll
        for (int j = 0; j < 2; j++) wmma::fill_fragment(acc[i][j], 0.f);

    const int KT = K / BK;
#pragma unroll
    for (int s = 0; s < STAGES - 1; s++) load_tile(s, s);

    for (int kt = 0; kt < KT; kt++) {
        if (kt <= KT - STAGES) cp_wait<STAGES - 2>(); else cp_wait<0>();
        __syncthreads();
        int nt = kt + STAGES - 1;
        if (nt < KT) load_tile(nt % STAGES, nt);

        __half* As = smh + (kt % STAGES) * STAGE_SZ;
        __half* Bs = As + AS_SZ;
#pragma unroll
        for (int kk = 0; kk < BK; kk += 16) {
            wmma::fragment<wmma::matrix_a, 16, 16, 16, __half, wmma::row_major> af[4];
            wmma::fragment<wmma::matrix_b, 16, 16, 16, __half, wmma::row_major> bf[2];
#pragma unroll
            for (int i = 0; i < 4; i++)
                wmma::load_matrix_sync(af[i], &As[(wm * 64 + i * 16) * ASTR + kk], ASTR);
#pragma unroll
            for (int j = 0; j < 2; j++)
                wmma::load_matrix_sync(bf[j], &Bs[kk * BSTR + wn * 32 + j * 16], BSTR);
#pragma unroll
            for (int i = 0; i < 4; i++)
#pragma unroll
                for (int j = 0; j < 2; j++)
                    wmma::mma_sync(acc[i][j], af[i], bf[j], acc[i][j]);
        }
    }
    __syncthreads();

#pragma unroll
    for (int i = 0; i < 4; i++)
#pragma unroll
        for (int j = 0; j < 2; j++)
            wmma::store_matrix_sync(&Cs[(wm * 64 + i * 16) * CSTR + wn * 32 + j * 16],
                                    acc[i][j], CSTR, wmma::mem_row_major);
    __syncthreads();

    const int cr = tid >> 4, cc = (tid & 15) * 8;
    float4 bv0 = *(const float4*)&bias[n0 + cc];
    float4 bv1 = *(const float4*)&bias[n0 + cc + 4];
#pragma unroll
    for (int it = 0; it < 8; it++) {
        int r = cr + it * 16;
        float4 v0 = *(float4*)&Cs[r * CSTR + cc];
        float4 v1 = *(float4*)&Cs[r * CSTR + cc + 4];
        v0.x += bv0.x; v0.y += bv0.y; v0.z += bv0.z; v0.w += bv0.w;
        v1.x += bv1.x; v1.y += bv1.y; v1.z += bv1.z; v1.w += bv1.w;
        if (outHalf) {
            __half2 h[4];
            h[0] = __floats2half2_rn(v0.x, v0.y);
            h[1] = __floats2half2_rn(v0.z, v0.w);
            h[2] = __floats2half2_rn(v1.x, v1.y);
            h[3] = __floats2half2_rn(v1.z, v1.w);
            *(uint4*)&Ch[(m0 + r) * Nn + n0 + cc] = *(uint4*)h;
        } else {
            *(float4*)&Cf[(m0 + r) * Nn + n0 + cc] = v0;
            *(float4*)&Cf[(m0 + r) * Nn + n0 + cc + 4] = v1;
        }
    }
}

// ---------------- flash-style window attention: register-resident softmax ----------------
// One CTA per (b,h); 13 warps; warp w owns rows 16w..16w+15 (full 208-col rows).
#define AKV 72   // halves per K/V smem row (64 + 8 pad; 144B stride -> conflict-free ldmatrix)
#define OFF_AVS  (208 * AKV * 2)                // 29952
#define OFF_ABI  (OFF_AVS + 208 * AKV * 2)      // 59904
#define OFF_AJQ  (OFF_ABI + 736 * 4)            // 62848
#define ATT_SMEM (OFF_AJQ + 196 * 4)            // 63632

__global__ void __launch_bounds__(416, 1) attn_kernel(
    const __half* __restrict__ qkv, const float* __restrict__ bias_table,
    __half* __restrict__ att)
{
    extern __shared__ char smraw[];
    __half* Ks    = (__half*)smraw;
    __half* Vs    = (__half*)(smraw + OFF_AVS);
    float*  biasS = (float*)(smraw + OFF_ABI);
    int*    jqr   = (int*)(smraw + OFF_AJQ);

    const int tid  = threadIdx.x;
    const int lane = tid & 31;
    const int warp = tid >> 5;                    // 0..12
    const int b = blockIdx.x >> 3;
    const int h = blockIdx.x & 7;

    const __half* base = qkv + (size_t)b * N_TOK * 1536 + h * DH;

    // ---- K, V -> smem; zero pad rows 196..207 ----
    for (int idx = tid; idx < N_TOK * 8; idx += 416) {
        int r = idx >> 3, c8 = (idx & 7) * 8;
        const __half* rp = base + (size_t)r * 1536;
        *(uint4*)&Ks[r * AKV + c8] = *(const uint4*)(rp + 512 + c8);
        *(uint4*)&Vs[r * AKV + c8] = *(const uint4*)(rp + 1024 + c8);
    }
    for (int idx = tid; idx < 12 * 8; idx += 416) {
        int r = 196 + (idx >> 3), c8 = (idx & 7) * 8;
        uint4 z = make_uint4(0, 0, 0, 0);
        *(uint4*)&Ks[r * AKV + c8] = z;
        *(uint4*)&Vs[r * AKV + c8] = z;
    }
    for (int t = tid; t < 729; t += 416) biasS[t] = bias_table[t * HEADS + h];
    for (int j = tid; j < 196; j += 416) {
        int jq = j / 14;
        jqr[j] = jq * 27 + (j - jq * 14);
    }
    __syncthreads();

    // ---- per-warp row ownership ----
    const int r0    = warp * 16;
    const int qrow  = r0 + (lane >> 2);        // owned row (and +8)
    const int qcol0 = (lane & 3) * 2;
    const int i0 = qrow, i1 = qrow + 8;
    const int rA0 = (i0 < N_TOK) ? i0 : 0;     // clamp for safe gmem reads
    const int rA1 = (i1 < N_TOK) ? i1 : 0;

    // ---- Q fragments from gmem (scaled by 0.125, exact in fp16) ----
    unsigned qa[4][4];
    {
        const __half2 qs2 = __floats2half2_rn(0.125f, 0.125f);
        const __half* q0 = base + (size_t)rA0 * 1536;
        const __half* q1 = base + (size_t)rA1 * 1536;
#pragma unroll
        for (int kc = 0; kc < 4; kc++) {
            __half2 v0 = __hmul2(*(const __half2*)(q0 + kc * 16 + qcol0),     qs2);
            __half2 v1 = __hmul2(*(const __half2*)(q1 + kc * 16 + qcol0),     qs2);
            __half2 v2 = __hmul2(*(const __half2*)(q0 + kc * 16 + 8 + qcol0), qs2);
            __half2 v3 = __hmul2(*(const __half2*)(q1 + kc * 16 + 8 + qcol0), qs2);
            qa[kc][0] = *(unsigned*)&v0;
            qa[kc][1] = *(unsigned*)&v1;
            qa[kc][2] = *(unsigned*)&v2;
            qa[kc][3] = *(unsigned*)&v3;
        }
    }

    // ---- S = Q @ K^T : 26 n-tiles x 4 k-chunks, accumulators in registers ----
    float sacc[26][4];
#pragma unroll
    for (int jt = 0; jt < 26; jt++)
#pragma unroll
        for (int c = 0; c < 4; c++) sacc[jt][c] = 0.f;

    const unsigned ks_base = (unsigned)__cvta_generic_to_shared(Ks);
    const unsigned vs_base = (unsigned)__cvta_generic_to_shared(Vs);
    const unsigned ka0 = ks_base + ((lane & 7) * AKV + 8 * ((lane >> 3) & 1)) * 2;
    const unsigned va0 = vs_base + ((lane & 15) * AKV) * 2;

#pragma unroll
    for (int kc = 0; kc < 4; kc++) {
#pragma unroll
        for (int jt = 0; jt < 26; jt++) {
            unsigned b0, b1;
            ldsm_x2(b0, b1, ka0 + (jt * 8 * AKV + kc * 16) * 2);
            mma16816(sacc[jt], qa[kc], b0, b1);
        }
    }

    // ---- softmax (register-resident; rows live in lane quads) ----
    const int ib0 = (i0 / 14) * 27 + (i0 % 14) + 364;
    const int ib1 = (i1 / 14) * 27 + (i1 % 14) + 364;
    float mx0 = -1e30f, mx1 = -1e30f;
#pragma unroll
    for (int jt = 0; jt < 26; jt++) {
#pragma unroll
        for (int e = 0; e < 2; e++) {
            int j = jt * 8 + qcol0 + e;
            if (j < N_TOK) {
                int jv = jqr[j];
                sacc[jt][e]     += biasS[ib0 - jv];
                sacc[jt][2 + e] += biasS[ib1 - jv];
            } else {
                sacc[jt][e] = -1e30f;
                sacc[jt][2 + e] = -1e30f;
            }
            mx0 = fmaxf(mx0, sacc[jt][e]);
            mx1 = fmaxf(mx1, sacc[jt][2 + e]);
        }
    }
    mx0 = fmaxf(mx0, __shfl_xor_sync(0xffffffffu, mx0, 1));
    mx0 = fmaxf(mx0, __shfl_xor_sync(0xffffffffu, mx0, 2));
    mx1 = fmaxf(mx1, __shfl_xor_sync(0xffffffffu, mx1, 1));
    mx1 = fmaxf(mx1, __shfl_xor_sync(0xffffffffu, mx1, 2));

    float s0 = 0.f, s1 = 0.f;
#pragma unroll
    for (int jt = 0; jt < 26; jt++) {
#pragma unroll
        for (int e = 0; e < 2; e++) {
            float p0 = __expf(sacc[jt][e] - mx0);
            float p1 = __expf(sacc[jt][2 + e] - mx1);
            sacc[jt][e] = p0;
            sacc[jt][2 + e] = p1;
            s0 += p0; s1 += p1;
        }
    }
    s0 += __shfl_xor_sync(0xffffffffu, s0, 1);
    s0 += __shfl_xor_sync(0xffffffffu, s0, 2);
    s1 += __shfl_xor_sync(0xffffffffu, s1, 1);
    s1 += __shfl_xor_sync(0xffffffffu, s1, 2);
    float rv0 = __frcp_rn(s0), rv1 = __frcp_rn(s1);

    // ---- convert S -> P fragments (C layout == A layout after pairing) ----
    unsigned p[52];
#pragma unroll
    for (int jt = 0; jt < 26; jt++) {
        __half2 h0 = __floats2half2_rn(sacc[jt][0] * rv0, sacc[jt][1] * rv0);
        __half2 h1 = __floats2half2_rn(sacc[jt][2] * rv1, sacc[jt][3] * rv1);
        p[2 * jt]     = *(unsigned*)&h0;
        p[2 * jt + 1] = *(unsigned*)&h1;
    }

    // ---- O = P @ V : 13 k-chunks x 8 n-tiles ----
    float oacc[8][4];
#pragma unroll
    for (int nt = 0; nt < 8; nt++)
#pragma unroll
        for (int c = 0; c < 4; c++) oacc[nt][c] = 0.f;

#pragma unroll
    for (int kt = 0; kt < 13; kt++) {
        const unsigned* a = &p[4 * kt];
#pragma unroll
        for (int nt = 0; nt < 8; nt++) {
            unsigned b0, b1;
            ldsm_x2_t(b0, b1, va0 + (kt * 16 * AKV + nt * 8) * 2);
            mma16816(oacc[nt], a, b0, b1);
        }
    }

    // ---- writeback (head-interleaved [B, N, 512], half) ----
    __half* ob = att + ((size_t)b * N_TOK) * 512 + h * DH;
    if (i0 < N_TOK) {
        __half* orow = ob + (size_t)i0 * 512;
#pragma unroll
        for (int nt = 0; nt < 8; nt++) {
            __half2 v = __floats2half2_rn(oacc[nt][0], oacc[nt][1]);
            *(__half2*)(orow + nt * 8 + qcol0) = v;
        }
    }
    if (i1 < N_TOK) {
        __half* orow = ob + (size_t)i1 * 512;
#pragma unroll
        for (int nt = 0; nt < 8; nt++) {
            __half2 v = __floats2half2_rn(oacc[nt][2], oacc[nt][3]);
            *(__half2*)(orow + nt * 8 + qcol0) = v;
        }
    }
}

// ---------------- launcher ----------------
extern "C" void kernel_launch(void* const* d_in, const int* in_sizes, int n_in,
                              void* d_out, int out_size)
{
    const float* x          = (const float*)d_in[0];
    const float* w_qkv      = (const float*)d_in[1];
    const float* b_qkv      = (const float*)d_in[2];
    const float* w_proj     = (const float*)d_in[3];
    const float* b_proj     = (const float*)d_in[4];
    const float* bias_table = (const float*)d_in[5];
    float* out = (float*)d_out;

    __half *xh, *qkvh, *atth, *wqkvh, *wprojh;
    cudaGetSymbolAddress((void**)&xh,     g_xh);
    cudaGetSymbolAddress((void**)&qkvh,   g_qkvh);
    cudaGetSymbolAddress((void**)&atth,   g_atth);
    cudaGetSymbolAddress((void**)&wqkvh,  g_wqkvh);
    cudaGetSymbolAddress((void**)&wprojh, g_wprojh);

    const int M = B_SZ * N_TOK;  // 100352

    const size_t PIPE_B = (size_t)STAGES * STAGE_SZ * 2;
    const size_t EPI_B  = (size_t)BM * CSTR * 4;
    const size_t GEMM_SMEM = PIPE_B > EPI_B ? PIPE_B : EPI_B;

    cudaFuncSetAttribute(gemm_bias_kernel, cudaFuncAttributeMaxDynamicSharedMemorySize,
                         (int)GEMM_SMEM);
    cudaFuncSetAttribute(attn_kernel, cudaFuncAttributeMaxDynamicSharedMemorySize,
                         (int)ATT_SMEM);

    { int n8 = M * 512 / 8;    cvt_kernel<<<(n8 + 255) / 256, 256>>>(x, xh, n8); }
    { int n8 = 512 * 1536 / 8; cvt_kernel<<<(n8 + 255) / 256, 256>>>(w_qkv, wqkvh, n8); }
    { int n8 = 512 * 512 / 8;  cvt_kernel<<<(n8 + 255) / 256, 256>>>(w_proj, wprojh, n8); }

    gemm_bias_kernel<<<dim3(1536 / BN, M / BM), 256, GEMM_SMEM>>>(
        xh, wqkvh, b_qkv, nullptr, qkvh, M, 1536, 512, 1);

    attn_kernel<<<B_SZ * HEADS, 416, ATT_SMEM>>>(qkvh, bias_table, atth);

    gemm_bias_kernel<<<dim3(512 / BN, M / BM), 256, GEMM_SMEM>>>(
        atth, wprojh, b_proj, out, nullptr, M, 512, 512, 0);
}